// round 13
// baseline (speedup 1.0000x reference)
#include <cuda_runtime.h>
#include <math_constants.h>
#include <cuda_fp16.h>
#include <cstdint>

#define BB 4
#define TT 2048
#define CC 768
#define HH 64
#define NS 4
#define BQM 64
#define BKN 64

__device__ __align__(16) __half g_qh[BB * TT * HH];
__device__ __align__(16) __half g_kh[BB * TT * HH];
__device__ __align__(16) __half g_vh[BB * TT * HH];
__device__ __align__(16) __half g_wth[3 * HH * CC];
__device__ __align__(16) __half g_poh[NS * BB * TT * HH];
__device__ float g_pm[NS * BB * TT];
__device__ float g_pl[NS * BB * TT];
__device__ int   g_cnt[BB * (TT / BQM)];   // 128 fixup counters

__device__ __forceinline__ void mma_f16(float* c, const uint32_t* a, uint32_t b0, uint32_t b1) {
    asm volatile(
        "mma.sync.aligned.m16n8k16.row.col.f32.f16.f16.f32 "
        "{%0,%1,%2,%3}, {%4,%5,%6,%7}, {%8,%9}, {%0,%1,%2,%3};"
        : "+f"(c[0]), "+f"(c[1]), "+f"(c[2]), "+f"(c[3])
        : "r"(a[0]), "r"(a[1]), "r"(a[2]), "r"(a[3]), "r"(b0), "r"(b1));
}
__device__ __forceinline__ uint32_t packh2(float x, float y) {
    __half2 h = __floats2half2_rn(x, y);
    return *(uint32_t*)&h;
}
__device__ __forceinline__ uint32_t hex2x2(uint32_t x) {
    uint32_t r; asm("ex2.approx.f16x2 %0, %1;" : "=r"(r) : "r"(x)); return r;
}
__device__ __forceinline__ uint32_t smem_u32(const void* p) {
    uint32_t a;
    asm("{ .reg .u64 t; cvta.to.shared.u64 t, %1; cvt.u32.u64 %0, t; }"
        : "=r"(a) : "l"(p));
    return a;
}
__device__ __forceinline__ void ldmatrix_x4(uint32_t* r, uint32_t addr) {
    asm volatile("ldmatrix.sync.aligned.m8n8.x4.shared.b16 {%0,%1,%2,%3}, [%4];"
        : "=r"(r[0]), "=r"(r[1]), "=r"(r[2]), "=r"(r[3]) : "r"(addr));
}
__device__ __forceinline__ void ldmatrix_x4t(uint32_t* r, uint32_t addr) {
    asm volatile("ldmatrix.sync.aligned.m8n8.x4.trans.shared.b16 {%0,%1,%2,%3}, [%4];"
        : "=r"(r[0]), "=r"(r[1]), "=r"(r[2]), "=r"(r[3]) : "r"(addr));
}
__device__ __forceinline__ void ldmatrix_x2(uint32_t& r0, uint32_t& r1, uint32_t addr) {
    asm volatile("ldmatrix.sync.aligned.m8n8.x2.shared.b16 {%0,%1}, [%2];"
        : "=r"(r0), "=r"(r1) : "r"(addr));
}
__device__ __forceinline__ float ex2f(float x) {
    float r; asm("ex2.approx.ftz.f32 %0, %1;" : "=f"(r) : "f"(x)); return r;
}
#define CP_ASYNC16(dst, src) \
    asm volatile("cp.async.cg.shared.global [%0], [%1], 16;" :: "r"(dst), "l"(src))
#define CP_COMMIT() asm volatile("cp.async.commit_group;" ::: "memory")
#define CP_WAIT0()  asm volatile("cp.async.wait_group 0;" ::: "memory")

// ---------------------------------------------------------------------------
// Prep: fused transposed weights Wt[n=192][k=768] as half. Also zeroes the
// fixup counters for this launch (runs before attn in stream order).
// ---------------------------------------------------------------------------
__global__ __launch_bounds__(256) void wt_kernel(
    const float* __restrict__ Wq,
    const float* __restrict__ Wk,
    const float* __restrict__ Wv)
{
    if (blockIdx.x == 0 && threadIdx.x < BB * (TT / BQM))
        g_cnt[threadIdx.x] = 0;
    int i = blockIdx.x * 256 + threadIdx.x;
    int n = i / CC;
    int k = i - n * CC;
    const float* W = (n < 64) ? Wq : (n < 128) ? Wk : Wv;
    g_wth[i] = __float2half_rn(W[k * HH + (n & 63)]);
}

// ---------------------------------------------------------------------------
// QKV via fp16 mma.sync, software-pipelined staging (proven R11/R12).
// ---------------------------------------------------------------------------
__global__ __launch_bounds__(256) void qkv_mma_kernel(const float* __restrict__ x)
{
    __shared__ __half As[2][32][40];
    __shared__ __half Bs[2][192][40];
    const uint32_t ABUF = 32 * 40 * 2;
    const uint32_t BBUF = 192 * 40 * 2;

    int tid = threadIdx.x;
    int wid = tid >> 5, lane = tid & 31;
    int g   = lane >> 2, tig = lane & 3;
    int mw  = wid >> 2, nw = wid & 3;
    int mt  = blockIdx.x;

    float acc[6][4];
#pragma unroll
    for (int t = 0; t < 6; ++t)
#pragma unroll
        for (int j = 0; j < 4; ++j) acc[t][j] = 0.f;

    uint32_t addrA = smem_u32(&As[0][(mw << 4) + (lane & 15)][(lane >> 4) << 3]);
    uint32_t addrB = smem_u32(&Bs[0][nw * 48 + (lane & 7)][((lane >> 3) & 1) << 3]);

    int ar  = tid >> 3;
    int akq = (tid & 7) << 2;
    const float* xrow = x + (size_t)(mt * 32 + ar) * CC + akq;

    float4 va = *(const float4*)xrow;
    uint4 vb[3];
#pragma unroll
    for (int j = 0; j < 3; ++j) {
        int u = tid + j * 256;
        int n = u >> 2, k8 = (u & 3) << 3;
        vb[j] = *(const uint4*)&g_wth[(size_t)n * CC + k8];
    }

    for (int it = 0; it < CC / 32; ++it) {
        int buf = it & 1;
        *(uint2*)&As[buf][ar][akq] = make_uint2(packh2(va.x, va.y), packh2(va.z, va.w));
#pragma unroll
        for (int j = 0; j < 3; ++j) {
            int u = tid + j * 256;
            int n = u >> 2, k8 = (u & 3) << 3;
            *(uint4*)&Bs[buf][n][k8] = vb[j];
        }
        __syncthreads();

        if (it + 1 < CC / 32) {
            int ck = (it + 1) * 32;
            va = *(const float4*)(xrow + ck);
#pragma unroll
            for (int j = 0; j < 3; ++j) {
                int u = tid + j * 256;
                int n = u >> 2, k8 = (u & 3) << 3;
                vb[j] = *(const uint4*)&g_wth[(size_t)n * CC + ck + k8];
            }
        }

        uint32_t aA = addrA + buf * ABUF;
        uint32_t aB = addrB + buf * BBUF;
#pragma unroll
        for (int ks = 0; ks < 2; ++ks) {
            uint32_t a[4];
            ldmatrix_x4(a, aA + ks * 32);
#pragma unroll
            for (int t = 0; t < 6; ++t) {
                uint32_t b0, b1;
                ldmatrix_x2(b0, b1, aB + t * (8 * 80) + ks * 32);
                mma_f16(acc[t], a, b0, b1);
            }
        }
    }

    int row0 = mt * 32 + (mw << 4) + g;
#pragma unroll
    for (int t = 0; t < 6; ++t) {
        int n0  = nw * 48 + t * 8;
        __half* G = (n0 < 64) ? g_qh : (n0 < 128) ? g_kh : g_vh;
        int ncol = (n0 & 63) + (tig << 1);
        *(uint32_t*)&G[(size_t)row0 * HH + ncol] = packh2(acc[t][0], acc[t][1]);
        *(uint32_t*)&G[(size_t)(row0 + 8) * HH + ncol] = packh2(acc[t][2], acc[t][3]);
    }
}

// ---------------------------------------------------------------------------
// Flash attention + fused split-k combine. Block = 64 q rows, 4 warps,
// grid = 32qt x 4b x 4splits = 512. Last-arriving split per (b,qt) combines
// the 4 partials (L2-hot) and writes the final output.
// ---------------------------------------------------------------------------
__global__ __launch_bounds__(128, 4) void attn_mma_kernel(float* __restrict__ out)
{
    int blk = blockIdx.x;
    int s   = blk & 3;
    int b   = (blk >> 2) & 3;
    int qt  = 31 - (blk >> 4);            // LPT
    int tid = threadIdx.x;
    int wid = tid >> 5, lane = tid & 31;
    int g   = lane >> 2, tig = lane & 3;

    int nkt = qt + 1;
    int t0  = (s * nkt) >> 2;
    int t1  = ((s + 1) * nkt) >> 2;

    __half* po = g_poh + ((size_t)(s * BB + b) * TT + qt * BQM) * HH;
    float* pm = g_pm + (size_t)(s * BB + b) * TT + qt * BQM;
    float* pl = g_pl + (size_t)(s * BB + b) * TT + qt * BQM;

    __shared__ __half Qh[64][72];
    __shared__ __half Kh[2][64][72];
    __shared__ __half Vh[2][64][72];
    __shared__ int is_last;

    if (t0 == t1) {
        // empty split: zero partials
        for (int i = tid; i < (BQM * HH) / 2; i += 128) ((uint32_t*)po)[i] = 0;
        if (tid < BQM) { pm[tid] = -CUDART_INF_F; pl[tid] = 0.f; }
    } else {
        // stage Q + first K/V tile
        {
            const __half* qsrc = g_qh + (size_t)(b * TT + qt * BQM) * HH;
            const __half* ks = g_kh + (size_t)(b * TT + t0 * BKN) * HH;
            const __half* vs = g_vh + (size_t)(b * TT + t0 * BKN) * HH;
#pragma unroll
            for (int i = 0; i < 4; ++i) {
                int u = tid + i * 128;            // < 512
                int r = u >> 3, c = (u & 7) << 3;
                CP_ASYNC16(smem_u32(&Qh[r][c]), qsrc + (size_t)r * HH + c);
                CP_ASYNC16(smem_u32(&Kh[0][r][c]), ks + (size_t)r * HH + c);
                CP_ASYNC16(smem_u32(&Vh[0][r][c]), vs + (size_t)r * HH + c);
            }
            CP_COMMIT();
            CP_WAIT0();
        }
        __syncthreads();

        uint32_t aq[4][4];
        {
            uint32_t addrQ = smem_u32(&Qh[wid * 16 + (lane & 15)][(lane >> 4) << 3]);
#pragma unroll
            for (int ks = 0; ks < 4; ++ks)
                ldmatrix_x4(aq[ks], addrQ + ks * 32);
        }

        uint32_t aKb = smem_u32(&Kh[0][(lane & 7) + ((lane >> 4) << 3)][((lane >> 3) & 1) << 3]);
        uint32_t aVb = smem_u32(&Vh[0][lane & 15][(lane >> 4) << 3]);
        const uint32_t bufstride = 64 * 72 * 2;

        float oc[8][4];
#pragma unroll
        for (int ht = 0; ht < 8; ++ht)
#pragma unroll
            for (int j = 0; j < 4; ++j) oc[ht][j] = 0.f;
        float m0 = -CUDART_INF_F, m1 = -CUDART_INF_F, l0 = 0.f, l1 = 0.f;

        int qrow0 = qt * BQM + wid * 16 + g;
        const float SCL2 = 0.125f * 1.4426950408889634f;

        int buf = 0;
        for (int kt = t0; kt < t1; ++kt) {
            if (kt + 1 < t1) {
                const __half* ks = g_kh + (size_t)(b * TT + (kt + 1) * BKN) * HH;
                const __half* vs = g_vh + (size_t)(b * TT + (kt + 1) * BKN) * HH;
                int nb = buf ^ 1;
#pragma unroll
                for (int i = 0; i < 4; ++i) {
                    int u = tid + i * 128;
                    int r = u >> 3, c = (u & 7) << 3;
                    CP_ASYNC16(smem_u32(&Kh[nb][r][c]), ks + (size_t)r * HH + c);
                    CP_ASYNC16(smem_u32(&Vh[nb][r][c]), vs + (size_t)r * HH + c);
                }
                CP_COMMIT();
            }

            uint32_t addrK = aKb + buf * bufstride;
            uint32_t addrV = aVb + buf * bufstride;

            float c[8][4];
#pragma unroll
            for (int ntp = 0; ntp < 4; ++ntp) {
                c[2 * ntp][0] = c[2 * ntp][1] = c[2 * ntp][2] = c[2 * ntp][3] = 0.f;
                c[2 * ntp + 1][0] = c[2 * ntp + 1][1] = c[2 * ntp + 1][2] = c[2 * ntp + 1][3] = 0.f;
#pragma unroll
                for (int ks = 0; ks < 4; ++ks) {
                    uint32_t r[4];
                    ldmatrix_x4(r, addrK + ntp * (16 * 144) + ks * 32);
                    mma_f16(c[2 * ntp],     aq[ks], r[0], r[1]);
                    mma_f16(c[2 * ntp + 1], aq[ks], r[2], r[3]);
                }
            }

            bool needmask = (kt == qt);
#pragma unroll
            for (int nt = 0; nt < 8; ++nt) {
                int kc = kt * BKN + nt * 8 + 2 * tig;
#pragma unroll
                for (int j = 0; j < 4; ++j) {
                    c[nt][j] *= SCL2;
                    if (needmask) {
                        int kg = kc + (j & 1);
                        int qg = (j < 2) ? qrow0 : qrow0 + 8;
                        if (kg > qg) c[nt][j] = -CUDART_INF_F;
                    }
                }
            }

            float rm0 = -CUDART_INF_F, rm1 = -CUDART_INF_F;
#pragma unroll
            for (int nt = 0; nt < 8; ++nt) {
                rm0 = fmaxf(rm0, fmaxf(c[nt][0], c[nt][1]));
                rm1 = fmaxf(rm1, fmaxf(c[nt][2], c[nt][3]));
            }
            rm0 = fmaxf(rm0, __shfl_xor_sync(0xffffffff, rm0, 1));
            rm0 = fmaxf(rm0, __shfl_xor_sync(0xffffffff, rm0, 2));
            rm1 = fmaxf(rm1, __shfl_xor_sync(0xffffffff, rm1, 1));
            rm1 = fmaxf(rm1, __shfl_xor_sync(0xffffffff, rm1, 2));

            float mn0 = fmaxf(m0, rm0), mn1 = fmaxf(m1, rm1);
            float mb0 = (mn0 == -CUDART_INF_F) ? 0.f : mn0;
            float mb1 = (mn1 == -CUDART_INF_F) ? 0.f : mn1;
            float corr0 = ex2f(m0 - mb0);
            float corr1 = ex2f(m1 - mb1);
            m0 = mn0; m1 = mn1;

            uint32_t ph[8][2];
            float rs0 = 0.f, rs1 = 0.f;
#pragma unroll
            for (int nt = 0; nt < 8; ++nt) {
                ph[nt][0] = hex2x2(packh2(c[nt][0] - mb0, c[nt][1] - mb0));
                ph[nt][1] = hex2x2(packh2(c[nt][2] - mb1, c[nt][3] - mb1));
                float2 f0 = __half22float2(*(const __half2*)&ph[nt][0]);
                float2 f1 = __half22float2(*(const __half2*)&ph[nt][1]);
                rs0 += f0.x + f0.y;
                rs1 += f1.x + f1.y;
            }
            rs0 += __shfl_xor_sync(0xffffffff, rs0, 1);
            rs0 += __shfl_xor_sync(0xffffffff, rs0, 2);
            rs1 += __shfl_xor_sync(0xffffffff, rs1, 1);
            rs1 += __shfl_xor_sync(0xffffffff, rs1, 2);
            l0 = l0 * corr0 + rs0;
            l1 = l1 * corr1 + rs1;

#pragma unroll
            for (int ht = 0; ht < 8; ++ht) {
                oc[ht][0] *= corr0; oc[ht][1] *= corr0;
                oc[ht][2] *= corr1; oc[ht][3] *= corr1;
            }
#pragma unroll
            for (int kk = 0; kk < 4; ++kk) {
                const uint32_t* pa = &ph[2 * kk][0];
#pragma unroll
                for (int htp = 0; htp < 4; ++htp) {
                    uint32_t r[4];
                    ldmatrix_x4t(r, addrV + kk * (16 * 144) + htp * 32);
                    mma_f16(oc[2 * htp],     pa, r[0], r[1]);
                    mma_f16(oc[2 * htp + 1], pa, r[2], r[3]);
                }
            }

            if (kt + 1 < t1) CP_WAIT0();
            __syncthreads();
            buf ^= 1;
        }

        int r0 = wid * 16 + g;
        int r1 = r0 + 8;
#pragma unroll
        for (int ht = 0; ht < 8; ++ht) {
            int col = ht * 8 + 2 * tig;
            *(uint32_t*)&po[(size_t)r0 * HH + col] = packh2(oc[ht][0], oc[ht][1]);
            *(uint32_t*)&po[(size_t)r1 * HH + col] = packh2(oc[ht][2], oc[ht][3]);
        }
        if (tig == 0) {
            pm[r0] = m0; pl[r0] = l0;
            pm[r1] = m1; pl[r1] = l1;
        }
    }

    // ---- split-k fixup: last-arriving block combines ----
    __threadfence();
    __syncthreads();
    if (tid == 0) {
        int old = atomicAdd(&g_cnt[b * (TT / BQM) + qt], 1);
        is_last = (old == NS - 1);
    }
    __syncthreads();
    if (!is_last) return;
    __threadfence();   // acquire: other splits' partials now visible

    const int MS = BB * TT;
    const int PS = BB * TT * HH;
    int rowbase = b * TT + qt * BQM;
    for (int u = tid; u < (BQM * HH) / 8; u += 128) {
        int r   = u >> 3;
        int col = (u & 7) << 3;
        int row = rowbase + r;

        float m0 = g_pm[row], m1 = g_pm[MS + row],
              m2 = g_pm[2 * MS + row], m3 = g_pm[3 * MS + row];
        float ms = fmaxf(fmaxf(m0, m1), fmaxf(m2, m3));
        float w[4] = {ex2f(m0 - ms), ex2f(m1 - ms), ex2f(m2 - ms), ex2f(m3 - ms)};
        float lt = w[0] * g_pl[row] + w[1] * g_pl[MS + row]
                 + w[2] * g_pl[2 * MS + row] + w[3] * g_pl[3 * MS + row];
        float inv = 1.f / lt;

        float o[8] = {0.f, 0.f, 0.f, 0.f, 0.f, 0.f, 0.f, 0.f};
        size_t base = (size_t)row * HH + col;
#pragma unroll
        for (int sp = 0; sp < 4; ++sp) {
            uint4 uu = *(const uint4*)&g_poh[(size_t)sp * PS + base];
            float2 p0 = __half22float2(*(const __half2*)&uu.x);
            float2 p1 = __half22float2(*(const __half2*)&uu.y);
            float2 p2 = __half22float2(*(const __half2*)&uu.z);
            float2 p3 = __half22float2(*(const __half2*)&uu.w);
            o[0] += w[sp] * p0.x; o[1] += w[sp] * p0.y;
            o[2] += w[sp] * p1.x; o[3] += w[sp] * p1.y;
            o[4] += w[sp] * p2.x; o[5] += w[sp] * p2.y;
            o[6] += w[sp] * p3.x; o[7] += w[sp] * p3.y;
        }
        *(float4*)&out[base]     = make_float4(o[0] * inv, o[1] * inv, o[2] * inv, o[3] * inv);
        *(float4*)&out[base + 4] = make_float4(o[4] * inv, o[5] * inv, o[6] * inv, o[7] * inv);
    }
}

extern "C" void kernel_launch(void* const* d_in, const int* in_sizes, int n_in,
                              void* d_out, int out_size)
{
    const float* x  = (const float*)d_in[0];
    const float* Wq = (const float*)d_in[1];
    const float* Wk = (const float*)d_in[2];
    const float* Wv = (const float*)d_in[3];
    float* out = (float*)d_out;

    wt_kernel<<<(3 * HH * CC) / 256, 256>>>(Wq, Wk, Wv);
    qkv_mma_kernel<<<(BB * TT) / 32, 256>>>(x);
    attn_mma_kernel<<<(TT / BQM) * BB * NS, 128>>>(out);
}

// round 14
// speedup vs baseline: 1.0677x; 1.0677x over previous
#include <cuda_runtime.h>
#include <math_constants.h>
#include <cuda_fp16.h>
#include <cstdint>

#define BB 4
#define TT 2048
#define CC 768
#define HH 64
#define NS 4
#define BQM 128
#define BKN 64

__device__ __align__(16) __half g_qh[BB * TT * HH];
__device__ __align__(16) __half g_kh[BB * TT * HH];
__device__ __align__(16) __half g_vh[BB * TT * HH];
__device__ __align__(16) __half g_wth[3 * HH * CC];
__device__ __align__(16) __half g_poh[NS * BB * TT * HH];
__device__ float g_pm[NS * BB * TT];
__device__ float g_pl[NS * BB * TT];

__device__ __forceinline__ void mma_f16(float* c, const uint32_t* a, uint32_t b0, uint32_t b1) {
    asm volatile(
        "mma.sync.aligned.m16n8k16.row.col.f32.f16.f16.f32 "
        "{%0,%1,%2,%3}, {%4,%5,%6,%7}, {%8,%9}, {%0,%1,%2,%3};"
        : "+f"(c[0]), "+f"(c[1]), "+f"(c[2]), "+f"(c[3])
        : "r"(a[0]), "r"(a[1]), "r"(a[2]), "r"(a[3]), "r"(b0), "r"(b1));
}
__device__ __forceinline__ uint32_t packh2(float x, float y) {
    __half2 h = __floats2half2_rn(x, y);
    return *(uint32_t*)&h;
}
__device__ __forceinline__ uint32_t hex2x2(uint32_t x) {
    uint32_t r; asm("ex2.approx.f16x2 %0, %1;" : "=r"(r) : "r"(x)); return r;
}
__device__ __forceinline__ uint32_t smem_u32(const void* p) {
    uint32_t a;
    asm("{ .reg .u64 t; cvta.to.shared.u64 t, %1; cvt.u32.u64 %0, t; }"
        : "=r"(a) : "l"(p));
    return a;
}
__device__ __forceinline__ void ldmatrix_x4(uint32_t* r, uint32_t addr) {
    asm volatile("ldmatrix.sync.aligned.m8n8.x4.shared.b16 {%0,%1,%2,%3}, [%4];"
        : "=r"(r[0]), "=r"(r[1]), "=r"(r[2]), "=r"(r[3]) : "r"(addr));
}
__device__ __forceinline__ void ldmatrix_x4t(uint32_t* r, uint32_t addr) {
    asm volatile("ldmatrix.sync.aligned.m8n8.x4.trans.shared.b16 {%0,%1,%2,%3}, [%4];"
        : "=r"(r[0]), "=r"(r[1]), "=r"(r[2]), "=r"(r[3]) : "r"(addr));
}
__device__ __forceinline__ float ex2f(float x) {
    float r; asm("ex2.approx.ftz.f32 %0, %1;" : "=f"(r) : "f"(x)); return r;
}
#define CP_ASYNC16(dst, src) \
    asm volatile("cp.async.cg.shared.global [%0], [%1], 16;" :: "r"(dst), "l"(src))
#define CP_COMMIT() asm volatile("cp.async.commit_group;" ::: "memory")
#define CP_WAIT0()  asm volatile("cp.async.wait_group 0;" ::: "memory")

// ---------------------------------------------------------------------------
// Prep: fused transposed weights Wt[n=192][k=768] as half, via smem tile
// transpose (coalesced reads along n, coalesced writes along k).
// grid = 3 matrices x 24 k-tiles = 72 blocks.
// ---------------------------------------------------------------------------
__global__ __launch_bounds__(256) void wt_kernel(
    const float* __restrict__ Wq,
    const float* __restrict__ Wk,
    const float* __restrict__ Wv)
{
    __shared__ float S[32][65];
    int blk = blockIdx.x;
    int sel = blk / 24;          // matrix
    int kt  = blk % 24;          // 32-wide k tile
    const float* W = (sel == 0) ? Wq : (sel == 1) ? Wk : Wv;
    int tid = threadIdx.x;

    // load 32 k-rows x 64 n-cols, coalesced along n
#pragma unroll
    for (int j = 0; j < 8; ++j) {
        int u = tid + j * 256;
        int r = u >> 6, c = u & 63;
        S[r][c] = W[(size_t)(kt * 32 + r) * HH + c];
    }
    __syncthreads();

    // store transposed: Wt[sel*64+n][kt*32+k], coalesced along k
#pragma unroll
    for (int j = 0; j < 8; ++j) {
        int u = tid + j * 256;
        int n = u >> 5, k = u & 31;
        g_wth[(size_t)(sel * 64 + n) * CC + kt * 32 + k] = __float2half_rn(S[k][n]);
    }
}

// ---------------------------------------------------------------------------
// QKV via fp16 mma.sync, software-pipelined staging; B-frags via x4 ldmatrix
// (one instruction serves two n8 tiles).
// ---------------------------------------------------------------------------
__global__ __launch_bounds__(256) void qkv_mma_kernel(const float* __restrict__ x)
{
    __shared__ __half As[2][32][40];
    __shared__ __half Bs[2][192][40];
    const uint32_t ABUF = 32 * 40 * 2;
    const uint32_t BBUF = 192 * 40 * 2;

    int tid = threadIdx.x;
    int wid = tid >> 5, lane = tid & 31;
    int g   = lane >> 2, tig = lane & 3;
    int mw  = wid >> 2, nw = wid & 3;
    int mt  = blockIdx.x;

    float acc[6][4];
#pragma unroll
    for (int t = 0; t < 6; ++t)
#pragma unroll
        for (int j = 0; j < 4; ++j) acc[t][j] = 0.f;

    uint32_t addrA = smem_u32(&As[0][(mw << 4) + (lane & 15)][(lane >> 4) << 3]);
    // x4 B base: rows (lane&7) + ((lane>>4)<<3), col half (lane>>3)&1
    uint32_t addrB = smem_u32(&Bs[0][nw * 48 + (lane & 7) + ((lane >> 4) << 3)][((lane >> 3) & 1) << 3]);

    int ar  = tid >> 3;
    int akq = (tid & 7) << 2;
    const float* xrow = x + (size_t)(mt * 32 + ar) * CC + akq;

    float4 va = *(const float4*)xrow;
    uint4 vb[3];
#pragma unroll
    for (int j = 0; j < 3; ++j) {
        int u = tid + j * 256;
        int n = u >> 2, k8 = (u & 3) << 3;
        vb[j] = *(const uint4*)&g_wth[(size_t)n * CC + k8];
    }

    for (int it = 0; it < CC / 32; ++it) {
        int buf = it & 1;
        *(uint2*)&As[buf][ar][akq] = make_uint2(packh2(va.x, va.y), packh2(va.z, va.w));
#pragma unroll
        for (int j = 0; j < 3; ++j) {
            int u = tid + j * 256;
            int n = u >> 2, k8 = (u & 3) << 3;
            *(uint4*)&Bs[buf][n][k8] = vb[j];
        }
        __syncthreads();

        if (it + 1 < CC / 32) {
            int ck = (it + 1) * 32;
            va = *(const float4*)(xrow + ck);
#pragma unroll
            for (int j = 0; j < 3; ++j) {
                int u = tid + j * 256;
                int n = u >> 2, k8 = (u & 3) << 3;
                vb[j] = *(const uint4*)&g_wth[(size_t)n * CC + ck + k8];
            }
        }

        uint32_t aA = addrA + buf * ABUF;
        uint32_t aB = addrB + buf * BBUF;
#pragma unroll
        for (int ks = 0; ks < 2; ++ks) {
            uint32_t a[4];
            ldmatrix_x4(a, aA + ks * 32);
#pragma unroll
            for (int tp = 0; tp < 3; ++tp) {
                uint32_t r[4];
                ldmatrix_x4(r, aB + tp * (16 * 80) + ks * 32);
                mma_f16(acc[2 * tp],     a, r[0], r[1]);
                mma_f16(acc[2 * tp + 1], a, r[2], r[3]);
            }
        }
    }

    int row0 = mt * 32 + (mw << 4) + g;
#pragma unroll
    for (int t = 0; t < 6; ++t) {
        int n0  = nw * 48 + t * 8;
        __half* G = (n0 < 64) ? g_qh : (n0 < 128) ? g_kh : g_vh;
        int ncol = (n0 & 63) + (tig << 1);
        *(uint32_t*)&G[(size_t)row0 * HH + ncol] = packh2(acc[t][0], acc[t][1]);
        *(uint32_t*)&G[(size_t)(row0 + 8) * HH + ncol] = packh2(acc[t][2], acc[t][3]);
    }
}

// ---------------------------------------------------------------------------
// Flash attention (R12-proven): fp16 mma, cp.async double-buffer, x4 ldmatrix
// B-frags, f16x2 exp2 softmax. BQM=128, 256 threads, kv-split x4.
// ---------------------------------------------------------------------------
__global__ __launch_bounds__(256, 2) void attn_mma_kernel()
{
    int blk = blockIdx.x;
    int s   = blk & 3;
    int b   = (blk >> 2) & 3;
    int qt  = 15 - (blk >> 4);
    int tid = threadIdx.x;
    int wid = tid >> 5, lane = tid & 31;
    int g   = lane >> 2, tig = lane & 3;

    int nkt = 2 * qt + 2;
    int t0  = (s * nkt) >> 2;
    int t1  = ((s + 1) * nkt) >> 2;

    __half* po = g_poh + ((size_t)(s * BB + b) * TT + qt * BQM) * HH;
    float* pm = g_pm + (size_t)(s * BB + b) * TT + qt * BQM;
    float* pl = g_pl + (size_t)(s * BB + b) * TT + qt * BQM;

    if (t0 == t1) {
        for (int i = tid; i < (BQM * HH) / 2; i += 256) ((uint32_t*)po)[i] = 0;
        if (tid < BQM) { pm[tid] = -CUDART_INF_F; pl[tid] = 0.f; }
        return;
    }

    __shared__ __half Qh[128][72];
    __shared__ __half Kh[2][64][72];
    __shared__ __half Vh[2][64][72];

    {
        const __half* qsrc = g_qh + (size_t)(b * TT + qt * BQM) * HH;
#pragma unroll
        for (int i = 0; i < 4; ++i) {
            int u = tid + i * 256;
            int r = u >> 3, c = (u & 7) << 3;
            CP_ASYNC16(smem_u32(&Qh[r][c]), qsrc + (size_t)r * HH + c);
        }
        const __half* ks = g_kh + (size_t)(b * TT + t0 * BKN) * HH;
        const __half* vs = g_vh + (size_t)(b * TT + t0 * BKN) * HH;
#pragma unroll
        for (int i = 0; i < 2; ++i) {
            int u = tid + i * 256;
            int r = u >> 3, c = (u & 7) << 3;
            CP_ASYNC16(smem_u32(&Kh[0][r][c]), ks + (size_t)r * HH + c);
            CP_ASYNC16(smem_u32(&Vh[0][r][c]), vs + (size_t)r * HH + c);
        }
        CP_COMMIT();
        CP_WAIT0();
    }
    __syncthreads();

    uint32_t aq[4][4];
    {
        uint32_t addrQ = smem_u32(&Qh[wid * 16 + (lane & 15)][(lane >> 4) << 3]);
#pragma unroll
        for (int ks = 0; ks < 4; ++ks)
            ldmatrix_x4(aq[ks], addrQ + ks * 32);
    }

    uint32_t aKb = smem_u32(&Kh[0][(lane & 7) + ((lane >> 4) << 3)][((lane >> 3) & 1) << 3]);
    uint32_t aVb = smem_u32(&Vh[0][lane & 15][(lane >> 4) << 3]);
    const uint32_t bufstride = 64 * 72 * 2;

    float oc[8][4];
#pragma unroll
    for (int ht = 0; ht < 8; ++ht)
#pragma unroll
        for (int j = 0; j < 4; ++j) oc[ht][j] = 0.f;
    float m0 = -CUDART_INF_F, m1 = -CUDART_INF_F, l0 = 0.f, l1 = 0.f;

    int qrow0 = qt * BQM + wid * 16 + g;
    const float SCL2 = 0.125f * 1.4426950408889634f;

    int buf = 0;
    for (int kt = t0; kt < t1; ++kt) {
        if (kt + 1 < t1) {
            const __half* ks = g_kh + (size_t)(b * TT + (kt + 1) * BKN) * HH;
            const __half* vs = g_vh + (size_t)(b * TT + (kt + 1) * BKN) * HH;
            int nb = buf ^ 1;
#pragma unroll
            for (int i = 0; i < 2; ++i) {
                int u = tid + i * 256;
                int r = u >> 3, c = (u & 7) << 3;
                CP_ASYNC16(smem_u32(&Kh[nb][r][c]), ks + (size_t)r * HH + c);
                CP_ASYNC16(smem_u32(&Vh[nb][r][c]), vs + (size_t)r * HH + c);
            }
            CP_COMMIT();
        }

        uint32_t addrK = aKb + buf * bufstride;
        uint32_t addrV = aVb + buf * bufstride;

        float c[8][4];
#pragma unroll
        for (int ntp = 0; ntp < 4; ++ntp) {
            c[2 * ntp][0] = c[2 * ntp][1] = c[2 * ntp][2] = c[2 * ntp][3] = 0.f;
            c[2 * ntp + 1][0] = c[2 * ntp + 1][1] = c[2 * ntp + 1][2] = c[2 * ntp + 1][3] = 0.f;
#pragma unroll
            for (int ks = 0; ks < 4; ++ks) {
                uint32_t r[4];
                ldmatrix_x4(r, addrK + ntp * (16 * 144) + ks * 32);
                mma_f16(c[2 * ntp],     aq[ks], r[0], r[1]);
                mma_f16(c[2 * ntp + 1], aq[ks], r[2], r[3]);
            }
        }

        bool needmask = (kt * BKN + 63 > qt * BQM);
#pragma unroll
        for (int nt = 0; nt < 8; ++nt) {
            int kc = kt * BKN + nt * 8 + 2 * tig;
#pragma unroll
            for (int j = 0; j < 4; ++j) {
                c[nt][j] *= SCL2;
                if (needmask) {
                    int kg = kc + (j & 1);
                    int qg = (j < 2) ? qrow0 : qrow0 + 8;
                    if (kg > qg) c[nt][j] = -CUDART_INF_F;
                }
            }
        }

        float rm0 = -CUDART_INF_F, rm1 = -CUDART_INF_F;
#pragma unroll
        for (int nt = 0; nt < 8; ++nt) {
            rm0 = fmaxf(rm0, fmaxf(c[nt][0], c[nt][1]));
            rm1 = fmaxf(rm1, fmaxf(c[nt][2], c[nt][3]));
        }
        rm0 = fmaxf(rm0, __shfl_xor_sync(0xffffffff, rm0, 1));
        rm0 = fmaxf(rm0, __shfl_xor_sync(0xffffffff, rm0, 2));
        rm1 = fmaxf(rm1, __shfl_xor_sync(0xffffffff, rm1, 1));
        rm1 = fmaxf(rm1, __shfl_xor_sync(0xffffffff, rm1, 2));

        float mn0 = fmaxf(m0, rm0), mn1 = fmaxf(m1, rm1);
        float mb0 = (mn0 == -CUDART_INF_F) ? 0.f : mn0;
        float mb1 = (mn1 == -CUDART_INF_F) ? 0.f : mn1;
        float corr0 = ex2f(m0 - mb0);
        float corr1 = ex2f(m1 - mb1);
        m0 = mn0; m1 = mn1;

        uint32_t ph[8][2];
        float rs0 = 0.f, rs1 = 0.f;
#pragma unroll
        for (int nt = 0; nt < 8; ++nt) {
            ph[nt][0] = hex2x2(packh2(c[nt][0] - mb0, c[nt][1] - mb0));
            ph[nt][1] = hex2x2(packh2(c[nt][2] - mb1, c[nt][3] - mb1));
            float2 f0 = __half22float2(*(const __half2*)&ph[nt][0]);
            float2 f1 = __half22float2(*(const __half2*)&ph[nt][1]);
            rs0 += f0.x + f0.y;
            rs1 += f1.x + f1.y;
        }
        rs0 += __shfl_xor_sync(0xffffffff, rs0, 1);
        rs0 += __shfl_xor_sync(0xffffffff, rs0, 2);
        rs1 += __shfl_xor_sync(0xffffffff, rs1, 1);
        rs1 += __shfl_xor_sync(0xffffffff, rs1, 2);
        l0 = l0 * corr0 + rs0;
        l1 = l1 * corr1 + rs1;

#pragma unroll
        for (int ht = 0; ht < 8; ++ht) {
            oc[ht][0] *= corr0; oc[ht][1] *= corr0;
            oc[ht][2] *= corr1; oc[ht][3] *= corr1;
        }
#pragma unroll
        for (int kk = 0; kk < 4; ++kk) {
            const uint32_t* pa = &ph[2 * kk][0];
#pragma unroll
            for (int htp = 0; htp < 4; ++htp) {
                uint32_t r[4];
                ldmatrix_x4t(r, addrV + kk * (16 * 144) + htp * 32);
                mma_f16(oc[2 * htp],     pa, r[0], r[1]);
                mma_f16(oc[2 * htp + 1], pa, r[2], r[3]);
            }
        }

        if (kt + 1 < t1) CP_WAIT0();
        __syncthreads();
        buf ^= 1;
    }

    int r0 = wid * 16 + g;
    int r1 = r0 + 8;
#pragma unroll
    for (int ht = 0; ht < 8; ++ht) {
        int col = ht * 8 + 2 * tig;
        *(uint32_t*)&po[(size_t)r0 * HH + col] = packh2(oc[ht][0], oc[ht][1]);
        *(uint32_t*)&po[(size_t)r1 * HH + col] = packh2(oc[ht][2], oc[ht][3]);
    }
    if (tig == 0) {
        pm[r0] = m0; pl[r0] = l0;
        pm[r1] = m1; pl[r1] = l1;
    }
}

// ---------------------------------------------------------------------------
// Combine kv-split partials: 8 elements per thread (uint4 per split).
// ---------------------------------------------------------------------------
__global__ __launch_bounds__(256) void combine_kernel(float* __restrict__ out)
{
    int i8  = blockIdx.x * 256 + threadIdx.x;
    int row = i8 >> 3;
    int col = (i8 & 7) << 3;

    const int MS = BB * TT;
    const int PS = BB * TT * HH;

    float m0 = g_pm[row], m1 = g_pm[MS + row],
          m2 = g_pm[2 * MS + row], m3 = g_pm[3 * MS + row];
    float ms = fmaxf(fmaxf(m0, m1), fmaxf(m2, m3));
    float w0 = ex2f(m0 - ms), w1 = ex2f(m1 - ms);
    float w2 = ex2f(m2 - ms), w3 = ex2f(m3 - ms);
    float lt = w0 * g_pl[row] + w1 * g_pl[MS + row]
             + w2 * g_pl[2 * MS + row] + w3 * g_pl[3 * MS + row];
    float inv = 1.f / lt;

    float o[8] = {0.f, 0.f, 0.f, 0.f, 0.f, 0.f, 0.f, 0.f};
    float w[4] = {w0, w1, w2, w3};
    size_t base = (size_t)row * HH + col;
#pragma unroll
    for (int s = 0; s < 4; ++s) {
        uint4 u = *(const uint4*)&g_poh[(size_t)s * PS + base];
        float2 p0 = __half22float2(*(const __half2*)&u.x);
        float2 p1 = __half22float2(*(const __half2*)&u.y);
        float2 p2 = __half22float2(*(const __half2*)&u.z);
        float2 p3 = __half22float2(*(const __half2*)&u.w);
        o[0] += w[s] * p0.x; o[1] += w[s] * p0.y;
        o[2] += w[s] * p1.x; o[3] += w[s] * p1.y;
        o[4] += w[s] * p2.x; o[5] += w[s] * p2.y;
        o[6] += w[s] * p3.x; o[7] += w[s] * p3.y;
    }
    *(float4*)&out[base]     = make_float4(o[0] * inv, o[1] * inv, o[2] * inv, o[3] * inv);
    *(float4*)&out[base + 4] = make_float4(o[4] * inv, o[5] * inv, o[6] * inv, o[7] * inv);
}

extern "C" void kernel_launch(void* const* d_in, const int* in_sizes, int n_in,
                              void* d_out, int out_size)
{
    const float* x  = (const float*)d_in[0];
    const float* Wq = (const float*)d_in[1];
    const float* Wk = (const float*)d_in[2];
    const float* Wv = (const float*)d_in[3];
    float* out = (float*)d_out;

    wt_kernel<<<72, 256>>>(Wq, Wk, Wv);
    qkv_mma_kernel<<<(BB * TT) / 32, 256>>>(x);
    attn_mma_kernel<<<16 * 4 * NS, 256>>>();
    combine_kernel<<<(BB * TT * HH) / 8 / 256, 256>>>(out);
}